// round 6
// baseline (speedup 1.0000x reference)
#include <cuda_runtime.h>
#include <cuda_fp16.h>

// GaussianWarpingScheme on GB300 — round 6.
// Pass 1: transpose im (B,C,H,W) f32 -> scratch (B,H,W,C) fp16 (32 MB).
// Pass 2: 256 threads = 64 pixels.
//   A: threads 0..63 compute per-pixel 2x2 weights + x-pair base (boundary-
//      correct slot remap) + clamped y rows, stage in smem.
//   B: 4 lanes/pixel = (xsel, channel-half). Each lane: 2x LDG.128 covering
//      8 channels of one x-tap for rows y0,y1 -> x-pair spans 64 contiguous
//      bytes -> 2 L1 wavefronts per pixel (was 4). fp32 accumulate.
//   C: combine x0/x1 partials via conflict-free smem planes; 128B-coalesced
//      channel-major stores.

#define Bn 8
#define Cn 16
#define Hn 256
#define Wn 256
#define HWn (Hn * Wn)

// 32 MB channel-last fp16 scratch: (B,H,W,C)
__device__ __half g_imH[(size_t)Bn * HWn * Cn];

// ---------------- Pass 1: (B,C,H,W) f32 -> (B,H,W,C) fp16 ----------------
__global__ void __launch_bounds__(256)
transpose_chw_hwc(const float* __restrict__ im)
{
    const int bh = blockIdx.x;          // 0 .. B*H-1
    const int b  = bh >> 8;
    const int h  = bh & (Hn - 1);
    const int wv = threadIdx.x;

    const float* src = im + ((size_t)(b * Cn) * Hn + h) * Wn + wv;
    __half* dst = g_imH + ((size_t)((b << 8) + h) * Wn + wv) * Cn;

    __half hv[Cn];
#pragma unroll
    for (int c = 0; c < Cn; c++)
        hv[c] = __float2half_rn(src[(size_t)c * HWn]);

    *(uint4*)(dst)     = *(const uint4*)(hv);
    *(uint4*)(dst + 8) = *(const uint4*)(hv + 8);
}

// ---------------- Pass 2 ----------------
#define CSTR  66                 // smem row stride (words)
#define PLANE (Cn * CSTR + 8)    // 1064: plane stride, bank-offset by 8

__global__ void __launch_bounds__(256)
gauss_warp_main(const float* __restrict__ w,
                float* __restrict__ out)
{
    __shared__ float s_pwx0[64], s_pwx1[64], s_wy0[64], s_wy1[64];
    __shared__ int   s_pack[64];
    __shared__ float s_part[2 * PLANE];

    const int tid   = threadIdx.x;
    const int pbase = blockIdx.x * 64;  // 64 consecutive pixels, same b/row
    const int b     = pbase >> 16;
    const int rem0  = pbase & (HWn - 1);

    // ---- phase A: per-pixel params (threads 0..63) ----
    if (tid < 64) {
        const int mrem = (pbase + tid) & (HWn - 1);
        const int mho  = mrem >> 8;
        const int mwo  = mrem & (Wn - 1);

        const float w0 = w[b * 2 * HWn + mrem];
        const float w1 = w[b * 2 * HWn + HWn + mrem];

        const float bx = -1.0f + (float)mwo * (2.0f / 255.0f);
        const float by = -1.0f + (float)mho * (2.0f / 255.0f);
        const float x = ((bx - w0) + 1.0f) * 0.5f * 255.0f;
        const float y = ((by - w1) + 1.0f) * 0.5f * 255.0f;
        const int ix = (int)floorf(x);
        const int iy = (int)floorf(y);
        const float fx = x - (float)ix;
        const float fy = y - (float)iy;

        const float wx0m = (ix     >= 0 && ix     < Wn) ? __expf(-8.0f * fx * fx)               : 0.0f;
        const float wx1m = (ix + 1 >= 0 && ix + 1 < Wn) ? __expf(-8.0f * (1.0f-fx) * (1.0f-fx)) : 0.0f;
        const float wy0m = (iy     >= 0 && iy     < Hn) ? __expf(-8.0f * fy * fy)               : 0.0f;
        const float wy1m = (iy + 1 >= 0 && iy + 1 < Hn) ? __expf(-8.0f * (1.0f-fy) * (1.0f-fy)) : 0.0f;

        // x-pair base with boundary-correct slot weights
        const int xb = min(max(ix, 0), Wn - 2);
        float pw0 = 0.0f, pw1 = 0.0f;
        if (ix     == xb)     pw0 += wx0m;     // normal case
        if (ix + 1 == xb)     pw0 += wx1m;     // ix = -1 -> slot0 gets wx1
        if (ix     == xb + 1) pw1 += wx0m;     // ix = 255 -> slot1 gets wx0
        if (ix + 1 == xb + 1) pw1 += wx1m;     // normal case

        s_pwx0[tid] = pw0;
        s_pwx1[tid] = pw1;
        s_wy0[tid]  = wy0m;
        s_wy1[tid]  = wy1m;

        const int yc0 = min(max(iy,     0), Hn - 1);
        const int yc1 = min(max(iy + 1, 0), Hn - 1);
        s_pack[tid] = xb | (yc0 << 8) | (yc1 << 16);
    }
    __syncthreads();

    // ---- phase B: 4 lanes per pixel = (xsel, channel-half) ----
    const int q    = tid >> 2;          // pixel 0..63
    const int g    = tid & 3;
    const int xsel = g >> 1;            // which x tap of the pair
    const int csel = g & 1;             // channel half: 0 -> ch 0..7, 1 -> ch 8..15

    const int pk  = s_pack[q];
    const int xb  =  pk        & 0xff;
    const int y0  = (pk >> 8)  & 0xff;
    const int y1  = (pk >> 16) & 0xff;

    const float wx = xsel ? s_pwx1[q] : s_pwx0[q];
    const float wA = wx * s_wy0[q];
    const float wB = wx * s_wy1[q];

    const __half* bh = g_imH + (size_t)b * HWn * Cn;
    const size_t lo = (size_t)(xb + xsel) * Cn + csel * 8;

    const uint4 ra = __ldg((const uint4*)(bh + ((size_t)(y0 << 8) * Cn) + lo));
    const uint4 rb = __ldg((const uint4*)(bh + ((size_t)(y1 << 8) * Cn) + lo));

    float acc[8];
    {
        float2 fa, fb;
        fa = __half22float2(*(const __half2*)&ra.x); fb = __half22float2(*(const __half2*)&rb.x);
        acc[0] = wA * fa.x + wB * fb.x;  acc[1] = wA * fa.y + wB * fb.y;
        fa = __half22float2(*(const __half2*)&ra.y); fb = __half22float2(*(const __half2*)&rb.y);
        acc[2] = wA * fa.x + wB * fb.x;  acc[3] = wA * fa.y + wB * fb.y;
        fa = __half22float2(*(const __half2*)&ra.z); fb = __half22float2(*(const __half2*)&rb.z);
        acc[4] = wA * fa.x + wB * fb.x;  acc[5] = wA * fa.y + wB * fb.y;
        fa = __half22float2(*(const __half2*)&ra.w); fb = __half22float2(*(const __half2*)&rb.w);
        acc[6] = wA * fa.x + wB * fb.x;  acc[7] = wA * fa.y + wB * fb.y;
    }

    // write partials: plane = xsel, rows = channels csel*8..csel*8+7, col = q
    {
        float* sp = s_part + xsel * PLANE + (csel * 8) * CSTR + q;
#pragma unroll
        for (int k = 0; k < 8; k++)
            sp[k * CSTR] = acc[k];
    }
    __syncthreads();

    // ---- phase C: combine x-partials, coalesced channel-major stores ----
    float* ob = out + (size_t)b * Cn * HWn + rem0;
#pragma unroll
    for (int k = 0; k < 4; k++) {
        const int idx = tid + k * 256;      // 0..1023
        const int c   = idx >> 6;
        const int px  = idx & 63;
        ob[(size_t)c * HWn + px] =
            s_part[c * CSTR + px] + s_part[PLANE + c * CSTR + px];
    }
}

extern "C" void kernel_launch(void* const* d_in, const int* in_sizes, int n_in,
                              void* d_out, int out_size)
{
    const float* im = (const float*)d_in[0];
    const float* w  = (const float*)d_in[1];
    if (n_in >= 2 && in_sizes[0] == Bn * 2 * HWn && in_sizes[1] == Bn * Cn * HWn) {
        im = (const float*)d_in[1];
        w  = (const float*)d_in[0];
    }
    float* out = (float*)d_out;

    transpose_chw_hwc<<<Bn * Hn, 256>>>(im);
    gauss_warp_main<<<(Bn * HWn) / 64, 256>>>(w, out);
}

// round 7
// speedup vs baseline: 1.1226x; 1.1226x over previous
#include <cuda_runtime.h>
#include <cuda_fp16.h>

// GaussianWarpingScheme on GB300 — round 7.
// Pass 1: transpose im (B,C,H,W) f32 -> scratch (B,H,W,C) fp16 (LTS-capped, unchanged).
// Pass 2: 256 threads = 128 pixels (2 lanes/pixel, 8 channels each).
//   A: threads 0..127 compute per-pixel 2x2 weight products (float4) + packed
//      indices (x-pair base with boundary slot remap), stage in smem.
//   B: each lane: 4x LDG.128 (8 ch of each tap), fp32 accumulate via packed
//      fma.rn.f32x2, direct 8x STG.32 to (B,C,H,W) output. No output staging.

#define Bn 8
#define Cn 16
#define Hn 256
#define Wn 256
#define HWn (Hn * Wn)

// 32 MB channel-last fp16 scratch: (B,H,W,C)
__device__ __half g_imH[(size_t)Bn * HWn * Cn];

// ---- packed f32x2 helpers ----
__device__ __forceinline__ unsigned long long f2pack(float lo, float hi) {
    unsigned long long r;
    asm("mov.b64 %0,{%1,%2};" : "=l"(r) : "f"(lo), "f"(hi));
    return r;
}
__device__ __forceinline__ unsigned long long h2f2(unsigned int h2) {
    const float2 f = __half22float2(*(const __half2*)&h2);
    return f2pack(f.x, f.y);
}
__device__ __forceinline__ unsigned long long fma2(unsigned long long a,
                                                   unsigned long long b,
                                                   unsigned long long c) {
    unsigned long long d;
    asm("fma.rn.f32x2 %0,%1,%2,%3;" : "=l"(d) : "l"(a), "l"(b), "l"(c));
    return d;
}
__device__ __forceinline__ unsigned long long mul2(unsigned long long a,
                                                   unsigned long long b) {
    unsigned long long d;
    asm("mul.rn.f32x2 %0,%1,%2;" : "=l"(d) : "l"(a), "l"(b));
    return d;
}
__device__ __forceinline__ float2 f2unpack(unsigned long long a) {
    float2 f;
    asm("mov.b64 {%0,%1},%2;" : "=f"(f.x), "=f"(f.y) : "l"(a));
    return f;
}

// ---------------- Pass 1: (B,C,H,W) f32 -> (B,H,W,C) fp16 ----------------
__global__ void __launch_bounds__(256)
transpose_chw_hwc(const float* __restrict__ im)
{
    const int bh = blockIdx.x;          // 0 .. B*H-1
    const int b  = bh >> 8;
    const int h  = bh & (Hn - 1);
    const int wv = threadIdx.x;

    const float* src = im + ((size_t)(b * Cn) * Hn + h) * Wn + wv;
    __half* dst = g_imH + ((size_t)((b << 8) + h) * Wn + wv) * Cn;

    __half hv[Cn];
#pragma unroll
    for (int c = 0; c < Cn; c++)
        hv[c] = __float2half_rn(src[(size_t)c * HWn]);

    *(uint4*)(dst)     = *(const uint4*)(hv);
    *(uint4*)(dst + 8) = *(const uint4*)(hv + 8);
}

// ---------------- Pass 2 ----------------
__global__ void __launch_bounds__(256)
gauss_warp_main(const float* __restrict__ w,
                float* __restrict__ out)
{
    __shared__ float4 s_w[128];         // (w00, w01, w10, w11) per pixel
    __shared__ int    s_pk[128];        // xb | y0<<8 | y1<<16

    const int tid   = threadIdx.x;
    const int pbase = blockIdx.x * 128; // 128 consecutive pixels, same b
    const int b     = pbase >> 16;

    // ---- phase A: per-pixel params (threads 0..127) ----
    if (tid < 128) {
        const int mrem = (pbase + tid) & (HWn - 1);
        const int mho  = mrem >> 8;
        const int mwo  = mrem & (Wn - 1);

        const float w0 = w[b * 2 * HWn + mrem];
        const float w1 = w[b * 2 * HWn + HWn + mrem];

        const float bx = -1.0f + (float)mwo * (2.0f / 255.0f);
        const float by = -1.0f + (float)mho * (2.0f / 255.0f);
        const float x = ((bx - w0) + 1.0f) * 0.5f * 255.0f;
        const float y = ((by - w1) + 1.0f) * 0.5f * 255.0f;
        const int ix = (int)floorf(x);
        const int iy = (int)floorf(y);
        const float fx = x - (float)ix;
        const float fy = y - (float)iy;

        const float wx0m = (ix     >= 0 && ix     < Wn) ? __expf(-8.0f * fx * fx)               : 0.0f;
        const float wx1m = (ix + 1 >= 0 && ix + 1 < Wn) ? __expf(-8.0f * (1.0f-fx) * (1.0f-fx)) : 0.0f;
        const float wy0m = (iy     >= 0 && iy     < Hn) ? __expf(-8.0f * fy * fy)               : 0.0f;
        const float wy1m = (iy + 1 >= 0 && iy + 1 < Hn) ? __expf(-8.0f * (1.0f-fy) * (1.0f-fy)) : 0.0f;

        // x-pair base with boundary-correct slot weights
        const int xb = min(max(ix, 0), Wn - 2);
        float pw0 = 0.0f, pw1 = 0.0f;
        if (ix     == xb)     pw0 += wx0m;
        if (ix + 1 == xb)     pw0 += wx1m;     // ix = -1
        if (ix     == xb + 1) pw1 += wx0m;     // ix = 255
        if (ix + 1 == xb + 1) pw1 += wx1m;

        s_w[tid] = make_float4(pw0 * wy0m, pw1 * wy0m, pw0 * wy1m, pw1 * wy1m);

        const int yc0 = min(max(iy,     0), Hn - 1);
        const int yc1 = min(max(iy + 1, 0), Hn - 1);
        s_pk[tid] = xb | (yc0 << 8) | (yc1 << 16);
    }
    __syncthreads();

    // ---- phase B: 2 lanes per pixel (csel = channel half) ----
    const int q    = tid >> 1;          // pixel 0..127
    const int csel = tid & 1;           // 0 -> ch 0..7, 1 -> ch 8..15

    const float4 wv = s_w[q];
    const int    pk = s_pk[q];
    const int xb =  pk        & 0xff;
    const int y0 = (pk >> 8)  & 0xff;
    const int y1 = (pk >> 16) & 0xff;

    const __half* bh = g_imH + (size_t)b * HWn * Cn;
    const __half* p0 = bh + (size_t)((y0 << 8) + xb) * Cn + csel * 8;
    const __half* p1 = bh + (size_t)((y1 << 8) + xb) * Cn + csel * 8;

    const uint4 r00 = __ldg((const uint4*)p0);        // (y0, x0) 8 ch
    const uint4 r01 = __ldg((const uint4*)p0 + 2);    // (y0, x1) +32B
    const uint4 r10 = __ldg((const uint4*)p1);        // (y1, x0)
    const uint4 r11 = __ldg((const uint4*)p1 + 2);    // (y1, x1)

    const unsigned long long W00 = f2pack(wv.x, wv.x);
    const unsigned long long W01 = f2pack(wv.y, wv.y);
    const unsigned long long W10 = f2pack(wv.z, wv.z);
    const unsigned long long W11 = f2pack(wv.w, wv.w);

    unsigned long long a0, a1, a2, a3;
    a0 = mul2(W00, h2f2(r00.x));
    a1 = mul2(W00, h2f2(r00.y));
    a2 = mul2(W00, h2f2(r00.z));
    a3 = mul2(W00, h2f2(r00.w));
    a0 = fma2(W01, h2f2(r01.x), a0);
    a1 = fma2(W01, h2f2(r01.y), a1);
    a2 = fma2(W01, h2f2(r01.z), a2);
    a3 = fma2(W01, h2f2(r01.w), a3);
    a0 = fma2(W10, h2f2(r10.x), a0);
    a1 = fma2(W10, h2f2(r10.y), a1);
    a2 = fma2(W10, h2f2(r10.z), a2);
    a3 = fma2(W10, h2f2(r10.w), a3);
    a0 = fma2(W11, h2f2(r11.x), a0);
    a1 = fma2(W11, h2f2(r11.y), a1);
    a2 = fma2(W11, h2f2(r11.z), a2);
    a3 = fma2(W11, h2f2(r11.w), a3);

    const float2 f0 = f2unpack(a0);
    const float2 f1 = f2unpack(a1);
    const float2 f2 = f2unpack(a2);
    const float2 f3 = f2unpack(a3);

    // direct stores: channels csel*8 .. csel*8+7 of pixel pbase+q
    const int rem = (pbase + q) & (HWn - 1);
    float* op = out + (size_t)b * Cn * HWn + (size_t)(csel * 8) * HWn + rem;
    op[0 * HWn] = f0.x;
    op[1 * HWn] = f0.y;
    op[2 * HWn] = f1.x;
    op[3 * HWn] = f1.y;
    op[4 * HWn] = f2.x;
    op[5 * HWn] = f2.y;
    op[6 * HWn] = f3.x;
    op[7 * HWn] = f3.y;
}

extern "C" void kernel_launch(void* const* d_in, const int* in_sizes, int n_in,
                              void* d_out, int out_size)
{
    const float* im = (const float*)d_in[0];
    const float* w  = (const float*)d_in[1];
    if (n_in >= 2 && in_sizes[0] == Bn * 2 * HWn && in_sizes[1] == Bn * Cn * HWn) {
        im = (const float*)d_in[1];
        w  = (const float*)d_in[0];
    }
    float* out = (float*)d_out;

    transpose_chw_hwc<<<Bn * Hn, 256>>>(im);
    gauss_warp_main<<<(Bn * HWn) / 128, 256>>>(w, out);
}

// round 8
// speedup vs baseline: 1.1658x; 1.0385x over previous
#include <cuda_runtime.h>
#include <cuda_fp16.h>

// GaussianWarpingScheme on GB300 — round 8.
// Pass 1: transpose im (B,C,H,W) f32 -> scratch (B,H,W,C) fp16 (LTS-capped).
// Pass 2: fully warp-independent. 2 lanes per pixel (8 channels each).
//   Each lane inlines its pixel's param math (SIMT dedups the instruction
//   cost across the lane pair), 4x LDG.128 gathers, FFMA2 accumulate,
//   8x STG.32. No smem, no __syncthreads, no cross-warp coupling.

#define Bn 8
#define Cn 16
#define Hn 256
#define Wn 256
#define HWn (Hn * Wn)

// 32 MB channel-last fp16 scratch: (B,H,W,C)
__device__ __half g_imH[(size_t)Bn * HWn * Cn];

// ---- packed f32x2 helpers ----
__device__ __forceinline__ unsigned long long f2pack(float lo, float hi) {
    unsigned long long r;
    asm("mov.b64 %0,{%1,%2};" : "=l"(r) : "f"(lo), "f"(hi));
    return r;
}
__device__ __forceinline__ unsigned long long h2f2(unsigned int h2) {
    const float2 f = __half22float2(*(const __half2*)&h2);
    return f2pack(f.x, f.y);
}
__device__ __forceinline__ unsigned long long fma2(unsigned long long a,
                                                   unsigned long long b,
                                                   unsigned long long c) {
    unsigned long long d;
    asm("fma.rn.f32x2 %0,%1,%2,%3;" : "=l"(d) : "l"(a), "l"(b), "l"(c));
    return d;
}
__device__ __forceinline__ unsigned long long mul2(unsigned long long a,
                                                   unsigned long long b) {
    unsigned long long d;
    asm("mul.rn.f32x2 %0,%1,%2;" : "=l"(d) : "l"(a), "l"(b));
    return d;
}
__device__ __forceinline__ float2 f2unpack(unsigned long long a) {
    float2 f;
    asm("mov.b64 {%0,%1},%2;" : "=f"(f.x), "=f"(f.y) : "l"(a));
    return f;
}

// ---------------- Pass 1: (B,C,H,W) f32 -> (B,H,W,C) fp16 ----------------
__global__ void __launch_bounds__(256)
transpose_chw_hwc(const float* __restrict__ im)
{
    const int bh = blockIdx.x;          // 0 .. B*H-1
    const int b  = bh >> 8;
    const int h  = bh & (Hn - 1);
    const int wv = threadIdx.x;

    const float* src = im + ((size_t)(b * Cn) * Hn + h) * Wn + wv;
    __half* dst = g_imH + ((size_t)((b << 8) + h) * Wn + wv) * Cn;

    __half hv[Cn];
#pragma unroll
    for (int c = 0; c < Cn; c++)
        hv[c] = __float2half_rn(src[(size_t)c * HWn]);

    *(uint4*)(dst)     = *(const uint4*)(hv);
    *(uint4*)(dst + 8) = *(const uint4*)(hv + 8);
}

// ---------------- Pass 2: warp-independent gather ----------------
__global__ void __launch_bounds__(256)
gauss_warp_main(const float* __restrict__ w,
                float* __restrict__ out)
{
    const int tid  = threadIdx.x;
    const int q    = tid >> 1;                    // pixel slot within block
    const int csel = tid & 1;                     // channel half

    const int p   = blockIdx.x * 128 + q;         // global pixel
    const int b   = p >> 16;
    const int rem = p & (HWn - 1);
    const int ho  = rem >> 8;
    const int wo  = rem & (Wn - 1);

    // ---- per-pixel params (lane pair duplicates; SIMT dedups instr cost) ----
    const float w0 = w[b * 2 * HWn + rem];                 // broadcast in pair
    const float w1 = w[b * 2 * HWn + HWn + rem];

    const float bx = -1.0f + (float)wo * (2.0f / 255.0f);
    const float by = -1.0f + (float)ho * (2.0f / 255.0f);
    const float x = ((bx - w0) + 1.0f) * 0.5f * 255.0f;
    const float y = ((by - w1) + 1.0f) * 0.5f * 255.0f;
    const int ix = (int)floorf(x);
    const int iy = (int)floorf(y);
    const float fx = x - (float)ix;
    const float fy = y - (float)iy;

    const float wx0m = (ix     >= 0 && ix     < Wn) ? __expf(-8.0f * fx * fx)               : 0.0f;
    const float wx1m = (ix + 1 >= 0 && ix + 1 < Wn) ? __expf(-8.0f * (1.0f-fx) * (1.0f-fx)) : 0.0f;
    const float wy0m = (iy     >= 0 && iy     < Hn) ? __expf(-8.0f * fy * fy)               : 0.0f;
    const float wy1m = (iy + 1 >= 0 && iy + 1 < Hn) ? __expf(-8.0f * (1.0f-fy) * (1.0f-fy)) : 0.0f;

    // x-pair base with boundary-correct slot weights
    const int xb = min(max(ix, 0), Wn - 2);
    float pw0 = 0.0f, pw1 = 0.0f;
    if (ix     == xb)     pw0 += wx0m;
    if (ix + 1 == xb)     pw0 += wx1m;            // ix = -1
    if (ix     == xb + 1) pw1 += wx0m;            // ix = 255
    if (ix + 1 == xb + 1) pw1 += wx1m;

    const int y0 = min(max(iy,     0), Hn - 1);
    const int y1 = min(max(iy + 1, 0), Hn - 1);

    // ---- gathers: 4x LDG.128 (8 channels of each tap) ----
    const __half* bh = g_imH + (size_t)b * HWn * Cn;
    const __half* p0 = bh + (size_t)((y0 << 8) + xb) * Cn + csel * 8;
    const __half* p1 = bh + (size_t)((y1 << 8) + xb) * Cn + csel * 8;

    const uint4 r00 = __ldg((const uint4*)p0);        // (y0, x0)
    const uint4 r01 = __ldg((const uint4*)p0 + 2);    // (y0, x1)
    const uint4 r10 = __ldg((const uint4*)p1);        // (y1, x0)
    const uint4 r11 = __ldg((const uint4*)p1 + 2);    // (y1, x1)

    const unsigned long long W00 = f2pack(pw0 * wy0m, pw0 * wy0m);
    const unsigned long long W01 = f2pack(pw1 * wy0m, pw1 * wy0m);
    const unsigned long long W10 = f2pack(pw0 * wy1m, pw0 * wy1m);
    const unsigned long long W11 = f2pack(pw1 * wy1m, pw1 * wy1m);

    unsigned long long a0, a1, a2, a3;
    a0 = mul2(W00, h2f2(r00.x));
    a1 = mul2(W00, h2f2(r00.y));
    a2 = mul2(W00, h2f2(r00.z));
    a3 = mul2(W00, h2f2(r00.w));
    a0 = fma2(W01, h2f2(r01.x), a0);
    a1 = fma2(W01, h2f2(r01.y), a1);
    a2 = fma2(W01, h2f2(r01.z), a2);
    a3 = fma2(W01, h2f2(r01.w), a3);
    a0 = fma2(W10, h2f2(r10.x), a0);
    a1 = fma2(W10, h2f2(r10.y), a1);
    a2 = fma2(W10, h2f2(r10.z), a2);
    a3 = fma2(W10, h2f2(r10.w), a3);
    a0 = fma2(W11, h2f2(r11.x), a0);
    a1 = fma2(W11, h2f2(r11.y), a1);
    a2 = fma2(W11, h2f2(r11.z), a2);
    a3 = fma2(W11, h2f2(r11.w), a3);

    const float2 f0 = f2unpack(a0);
    const float2 f1 = f2unpack(a1);
    const float2 f2 = f2unpack(a2);
    const float2 f3 = f2unpack(a3);

    // ---- direct stores: channels csel*8 .. csel*8+7 ----
    float* op = out + (size_t)b * Cn * HWn + (size_t)(csel * 8) * HWn + rem;
    op[0 * HWn] = f0.x;
    op[1 * HWn] = f0.y;
    op[2 * HWn] = f1.x;
    op[3 * HWn] = f1.y;
    op[4 * HWn] = f2.x;
    op[5 * HWn] = f2.y;
    op[6 * HWn] = f3.x;
    op[7 * HWn] = f3.y;
}

extern "C" void kernel_launch(void* const* d_in, const int* in_sizes, int n_in,
                              void* d_out, int out_size)
{
    const float* im = (const float*)d_in[0];
    const float* w  = (const float*)d_in[1];
    if (n_in >= 2 && in_sizes[0] == Bn * 2 * HWn && in_sizes[1] == Bn * Cn * HWn) {
        im = (const float*)d_in[1];
        w  = (const float*)d_in[0];
    }
    float* out = (float*)d_out;

    transpose_chw_hwc<<<Bn * Hn, 256>>>(im);
    gauss_warp_main<<<(Bn * HWn) / 128, 256>>>(w, out);
}

// round 9
// speedup vs baseline: 1.2208x; 1.0472x over previous
#include <cuda_runtime.h>
#include <cuda_fp16.h>

// GaussianWarpingScheme on GB300 — round 9.
// Pass 1: transpose im (B,C,H,W) f32 -> scratch (B,H,W,C) fp16 (LTS-capped).
// Pass 2: warp-independent, 2 pixels per lane (ILP=2), 8 channels per lane.
//   All 8 gather LDG.128s issued up front (MLP=8/lane), FFMA2 accumulate,
//   16x STG.32. No smem, no barriers.

#define Bn 8
#define Cn 16
#define Hn 256
#define Wn 256
#define HWn (Hn * Wn)

// 32 MB channel-last fp16 scratch: (B,H,W,C)
__device__ __half g_imH[(size_t)Bn * HWn * Cn];

// ---- packed f32x2 helpers ----
__device__ __forceinline__ unsigned long long f2pack(float lo, float hi) {
    unsigned long long r;
    asm("mov.b64 %0,{%1,%2};" : "=l"(r) : "f"(lo), "f"(hi));
    return r;
}
__device__ __forceinline__ unsigned long long h2f2(unsigned int h2) {
    const float2 f = __half22float2(*(const __half2*)&h2);
    return f2pack(f.x, f.y);
}
__device__ __forceinline__ unsigned long long fma2(unsigned long long a,
                                                   unsigned long long b,
                                                   unsigned long long c) {
    unsigned long long d;
    asm("fma.rn.f32x2 %0,%1,%2,%3;" : "=l"(d) : "l"(a), "l"(b), "l"(c));
    return d;
}
__device__ __forceinline__ unsigned long long mul2(unsigned long long a,
                                                   unsigned long long b) {
    unsigned long long d;
    asm("mul.rn.f32x2 %0,%1,%2;" : "=l"(d) : "l"(a), "l"(b));
    return d;
}
__device__ __forceinline__ float2 f2unpack(unsigned long long a) {
    float2 f;
    asm("mov.b64 {%0,%1},%2;" : "=f"(f.x), "=f"(f.y) : "l"(a));
    return f;
}

// ---------------- Pass 1: (B,C,H,W) f32 -> (B,H,W,C) fp16 ----------------
__global__ void __launch_bounds__(256)
transpose_chw_hwc(const float* __restrict__ im)
{
    const int bh = blockIdx.x;          // 0 .. B*H-1
    const int b  = bh >> 8;
    const int h  = bh & (Hn - 1);
    const int wv = threadIdx.x;

    const float* src = im + ((size_t)(b * Cn) * Hn + h) * Wn + wv;
    __half* dst = g_imH + ((size_t)((b << 8) + h) * Wn + wv) * Cn;

    __half hv[Cn];
#pragma unroll
    for (int c = 0; c < Cn; c++)
        hv[c] = __float2half_rn(src[(size_t)c * HWn]);

    *(uint4*)(dst)     = *(const uint4*)(hv);
    *(uint4*)(dst + 8) = *(const uint4*)(hv + 8);
}

// ---------------- Pass 2: warp-independent, 2 px/lane ----------------
struct PixParams {
    unsigned long long W00, W01, W10, W11;   // packed tap weights
    const __half* p0;                        // row y0, x-pair base (+csel half)
    const __half* p1;                        // row y1
    float* op;                               // output base (channel csel*8)
};

__device__ __forceinline__ PixParams
pix_params(int p, int csel, const float* __restrict__ w, float* __restrict__ out)
{
    const int b   = p >> 16;
    const int rem = p & (HWn - 1);
    const int ho  = rem >> 8;
    const int wo  = rem & (Wn - 1);

    const float w0 = w[b * 2 * HWn + rem];
    const float w1 = w[b * 2 * HWn + HWn + rem];

    const float bx = -1.0f + (float)wo * (2.0f / 255.0f);
    const float by = -1.0f + (float)ho * (2.0f / 255.0f);
    const float x = ((bx - w0) + 1.0f) * 0.5f * 255.0f;
    const float y = ((by - w1) + 1.0f) * 0.5f * 255.0f;
    const int ix = (int)floorf(x);
    const int iy = (int)floorf(y);
    const float fx = x - (float)ix;
    const float fy = y - (float)iy;

    const float wx0m = (ix     >= 0 && ix     < Wn) ? __expf(-8.0f * fx * fx)               : 0.0f;
    const float wx1m = (ix + 1 >= 0 && ix + 1 < Wn) ? __expf(-8.0f * (1.0f-fx) * (1.0f-fx)) : 0.0f;
    const float wy0m = (iy     >= 0 && iy     < Hn) ? __expf(-8.0f * fy * fy)               : 0.0f;
    const float wy1m = (iy + 1 >= 0 && iy + 1 < Hn) ? __expf(-8.0f * (1.0f-fy) * (1.0f-fy)) : 0.0f;

    // x-pair base with boundary-correct slot weights
    const int xb = min(max(ix, 0), Wn - 2);
    float pw0 = 0.0f, pw1 = 0.0f;
    if (ix     == xb)     pw0 += wx0m;
    if (ix + 1 == xb)     pw0 += wx1m;            // ix = -1
    if (ix     == xb + 1) pw1 += wx0m;            // ix = 255
    if (ix + 1 == xb + 1) pw1 += wx1m;

    const int y0 = min(max(iy,     0), Hn - 1);
    const int y1 = min(max(iy + 1, 0), Hn - 1);

    PixParams r;
    r.W00 = f2pack(pw0 * wy0m, pw0 * wy0m);
    r.W01 = f2pack(pw1 * wy0m, pw1 * wy0m);
    r.W10 = f2pack(pw0 * wy1m, pw0 * wy1m);
    r.W11 = f2pack(pw1 * wy1m, pw1 * wy1m);

    const __half* bh = g_imH + (size_t)b * HWn * Cn;
    r.p0 = bh + (size_t)((y0 << 8) + xb) * Cn + csel * 8;
    r.p1 = bh + (size_t)((y1 << 8) + xb) * Cn + csel * 8;
    r.op = out + (size_t)b * Cn * HWn + (size_t)(csel * 8) * HWn + rem;
    return r;
}

__global__ void __launch_bounds__(256)
gauss_warp_main(const float* __restrict__ w,
                float* __restrict__ out)
{
    const int tid  = threadIdx.x;
    const int q    = tid >> 1;                    // pixel slot 0..127
    const int csel = tid & 1;                     // channel half

    const int pA = blockIdx.x * 256 + q;          // first pixel
    const int pB = pA + 128;                      // second pixel

    const PixParams a = pix_params(pA, csel, w, out);
    const PixParams bp = pix_params(pB, csel, w, out);

    // ---- issue all 8 gathers up front (MLP = 8 per lane) ----
    const uint4 a00 = __ldg((const uint4*)a.p0);
    const uint4 a01 = __ldg((const uint4*)a.p0 + 2);
    const uint4 a10 = __ldg((const uint4*)a.p1);
    const uint4 a11 = __ldg((const uint4*)a.p1 + 2);
    const uint4 b00 = __ldg((const uint4*)bp.p0);
    const uint4 b01 = __ldg((const uint4*)bp.p0 + 2);
    const uint4 b10 = __ldg((const uint4*)bp.p1);
    const uint4 b11 = __ldg((const uint4*)bp.p1 + 2);

    // ---- pixel A accumulate ----
    unsigned long long s0, s1, s2, s3;
    s0 = mul2(a.W00, h2f2(a00.x));
    s1 = mul2(a.W00, h2f2(a00.y));
    s2 = mul2(a.W00, h2f2(a00.z));
    s3 = mul2(a.W00, h2f2(a00.w));
    s0 = fma2(a.W01, h2f2(a01.x), s0);
    s1 = fma2(a.W01, h2f2(a01.y), s1);
    s2 = fma2(a.W01, h2f2(a01.z), s2);
    s3 = fma2(a.W01, h2f2(a01.w), s3);
    s0 = fma2(a.W10, h2f2(a10.x), s0);
    s1 = fma2(a.W10, h2f2(a10.y), s1);
    s2 = fma2(a.W10, h2f2(a10.z), s2);
    s3 = fma2(a.W10, h2f2(a10.w), s3);
    s0 = fma2(a.W11, h2f2(a11.x), s0);
    s1 = fma2(a.W11, h2f2(a11.y), s1);
    s2 = fma2(a.W11, h2f2(a11.z), s2);
    s3 = fma2(a.W11, h2f2(a11.w), s3);
    {
        const float2 f0 = f2unpack(s0);
        const float2 f1 = f2unpack(s1);
        const float2 f2 = f2unpack(s2);
        const float2 f3 = f2unpack(s3);
        a.op[0 * HWn] = f0.x;  a.op[1 * HWn] = f0.y;
        a.op[2 * HWn] = f1.x;  a.op[3 * HWn] = f1.y;
        a.op[4 * HWn] = f2.x;  a.op[5 * HWn] = f2.y;
        a.op[6 * HWn] = f3.x;  a.op[7 * HWn] = f3.y;
    }

    // ---- pixel B accumulate ----
    s0 = mul2(bp.W00, h2f2(b00.x));
    s1 = mul2(bp.W00, h2f2(b00.y));
    s2 = mul2(bp.W00, h2f2(b00.z));
    s3 = mul2(bp.W00, h2f2(b00.w));
    s0 = fma2(bp.W01, h2f2(b01.x), s0);
    s1 = fma2(bp.W01, h2f2(b01.y), s1);
    s2 = fma2(bp.W01, h2f2(b01.z), s2);
    s3 = fma2(bp.W01, h2f2(b01.w), s3);
    s0 = fma2(bp.W10, h2f2(b10.x), s0);
    s1 = fma2(bp.W10, h2f2(b10.y), s1);
    s2 = fma2(bp.W10, h2f2(b10.z), s2);
    s3 = fma2(bp.W10, h2f2(b10.w), s3);
    s0 = fma2(bp.W11, h2f2(b11.x), s0);
    s1 = fma2(bp.W11, h2f2(b11.y), s1);
    s2 = fma2(bp.W11, h2f2(b11.z), s2);
    s3 = fma2(bp.W11, h2f2(b11.w), s3);
    {
        const float2 f0 = f2unpack(s0);
        const float2 f1 = f2unpack(s1);
        const float2 f2 = f2unpack(s2);
        const float2 f3 = f2unpack(s3);
        bp.op[0 * HWn] = f0.x;  bp.op[1 * HWn] = f0.y;
        bp.op[2 * HWn] = f1.x;  bp.op[3 * HWn] = f1.y;
        bp.op[4 * HWn] = f2.x;  bp.op[5 * HWn] = f2.y;
        bp.op[6 * HWn] = f3.x;  bp.op[7 * HWn] = f3.y;
    }
}

extern "C" void kernel_launch(void* const* d_in, const int* in_sizes, int n_in,
                              void* d_out, int out_size)
{
    const float* im = (const float*)d_in[0];
    const float* w  = (const float*)d_in[1];
    if (n_in >= 2 && in_sizes[0] == Bn * 2 * HWn && in_sizes[1] == Bn * Cn * HWn) {
        im = (const float*)d_in[1];
        w  = (const float*)d_in[0];
    }
    float* out = (float*)d_out;

    transpose_chw_hwc<<<Bn * Hn, 256>>>(im);
    gauss_warp_main<<<(Bn * HWn) / 256, 256>>>(w, out);
}